// round 4
// baseline (speedup 1.0000x reference)
#include <cuda_runtime.h>
#include <cstdint>

#define B_   64
#define L_   512
#define E_   512
#define HL_  1024
#define HS_  256
#define NC_  5

// ---------- device scratch (static; no runtime allocation) ----------
__device__ float g_gl[(size_t)L_ * B_ * 4 * HL_];   // gates large: [t][b][4096]
__device__ float g_gs[(size_t)L_ * B_ * 4 * HS_];   // gates small: [t][b][1024]
__device__ float g_r [L_ * B_ * 2];                 // gumbel weights [t][b][2]
__device__ float g_hl[HL_ * B_];                    // states transposed [k][b]
__device__ float g_cl[HL_ * B_];
__device__ float g_hs[HS_ * B_];
__device__ float g_cs[HS_ * B_];
__device__ unsigned int g_bar_arrive = 0;
__device__ unsigned int g_bar_gen    = 0;

__device__ __forceinline__ float sigf(float x) { return 1.0f / (1.0f + expf(-x)); }

__device__ __forceinline__ void grid_sync(void) {
    __syncthreads();
    if (threadIdx.x == 0) {
        unsigned int gen = *((volatile unsigned int*)&g_bar_gen);
        __threadfence();
        unsigned int a = atomicAdd(&g_bar_arrive, 1u);
        if (a == gridDim.x - 1) {
            g_bar_arrive = 0;
            __threadfence();
            atomicAdd(&g_bar_gen, 1u);
        } else {
            while (*((volatile unsigned int*)&g_bar_gen) == gen) { __nanosleep(64); }
        }
        __threadfence();
    }
    __syncthreads();
}

// ---------- init: gumbel-softmax r, zero recurrent state ----------
__global__ void k_init(const float* __restrict__ gu) {
    int n  = gridDim.x * blockDim.x;
    int id = blockIdx.x * blockDim.x + threadIdx.x;
    for (int q = id; q < B_ * L_; q += n) {            // q = b*L + t (gumbel_u is [B,L,2])
        int b = q >> 9, t = q & 511;
        float a0 = -logf(-logf(gu[q * 2 + 0]));
        float a1 = -logf(-logf(gu[q * 2 + 1]));
        float m  = fmaxf(a0, a1);
        float e0 = expf(a0 - m), e1 = expf(a1 - m);
        float inv = 1.0f / (e0 + e1);
        g_r[(t * B_ + b) * 2 + 0] = e0 * inv;
        g_r[(t * B_ + b) * 2 + 1] = e1 * inv;
    }
    for (int q = id; q < HL_ * B_; q += n) { g_hl[q] = 0.f; g_cl[q] = 0.f; }
    for (int q = id; q < HS_ * B_; q += n) { g_hs[q] = 0.f; g_cs[q] = 0.f; }
}

// ---------- input-gate GEMM fused with embedding gather ----------
// out[m][j] = sum_k emb[tok(m)][k]*Wih[j][k] + bih[j]+bhh[j];  m=t*B+b, M=32768, K=512
// tile 64m x 128j, BK=32, 256 thr, 8x4 per thread (j strided by 32)
template <int NTOT>
__global__ void __launch_bounds__(256)
k_ingemm(const int* __restrict__ x, const float* __restrict__ emb,
         const float* __restrict__ Wih, const float* __restrict__ bih,
         const float* __restrict__ bhh, float* __restrict__ out)
{
    __shared__ float As[32][65];
    __shared__ float Ws[128][33];
    __shared__ int   toks[64];
    int tid = threadIdx.x, warp = tid >> 5, lane = tid & 31;
    int m0 = blockIdx.y * 64, j0 = blockIdx.x * 128, r0i = warp * 8;

    if (tid < 64) { int m = m0 + tid; toks[tid] = x[(m & 63) * L_ + (m >> 6)]; }
    __syncthreads();

    float acc[8][4];
#pragma unroll
    for (int r = 0; r < 8; ++r)
#pragma unroll
        for (int c = 0; c < 4; ++c) acc[r][c] = 0.f;

    for (int ks = 0; ks < E_; ks += 32) {
#pragma unroll
        for (int i = tid; i < 64 * 32; i += 256) {
            int mm = i >> 5, kk = i & 31;
            As[kk][mm] = emb[(size_t)toks[mm] * E_ + ks + kk];
        }
#pragma unroll
        for (int i = tid; i < 128 * 32; i += 256) {
            int jj = i >> 5, kk = i & 31;
            Ws[jj][kk] = Wih[(size_t)(j0 + jj) * E_ + ks + kk];
        }
        __syncthreads();
#pragma unroll 8
        for (int kk = 0; kk < 32; ++kk) {
            float wv[4], av[8];
#pragma unroll
            for (int c = 0; c < 4; ++c) wv[c] = Ws[lane + 32 * c][kk];
#pragma unroll
            for (int r = 0; r < 8; ++r) av[r] = As[kk][r0i + r];
#pragma unroll
            for (int r = 0; r < 8; ++r)
#pragma unroll
                for (int c = 0; c < 4; ++c) acc[r][c] += av[r] * wv[c];
        }
        __syncthreads();
    }
#pragma unroll
    for (int c = 0; c < 4; ++c) {
        int j = j0 + lane + 32 * c;
        float bias = bih[j] + bhh[j];
#pragma unroll
        for (int r = 0; r < 8; ++r)
            out[(size_t)(m0 + r0i + r) * NTOT + j] = acc[r][c] + bias;
    }
}

// ---------- p_t embedding part: out_p[b*L+t][c] = b_p[c] + e . W_p[c][0:512] ----------
__global__ void __launch_bounds__(256)
k_pe(const int* __restrict__ x, const float* __restrict__ emb,
     const float* __restrict__ Wp, const float* __restrict__ bp,
     float* __restrict__ out_p)
{
    int gw = (blockIdx.x * blockDim.x + threadIdx.x) >> 5;   // gw = b*L + t
    int lane = threadIdx.x & 31;
    if (gw >= B_ * L_) return;
    const float* e = emb + (size_t)x[gw] * E_;
    float s0 = 0.f, s1 = 0.f;
    for (int k = lane; k < E_; k += 32) {
        float ev = e[k];
        s0 += ev * Wp[k];
        s1 += ev * Wp[2560 + k];
    }
#pragma unroll
    for (int o = 16; o; o >>= 1) {
        s0 += __shfl_down_sync(0xffffffffu, s0, o);
        s1 += __shfl_down_sync(0xffffffffu, s1, o);
    }
    if (lane == 0) {
        out_p[(size_t)gw * 2 + 0] = s0 + bp[0];
        out_p[(size_t)gw * 2 + 1] = s1 + bp[1];
    }
}

// ---------- persistent recurrence ----------
// phase1: K-split recurrent GEMM -> RED.ADD into gate buffers (128 large + 16 small tiles)
// phase2: fused LSTM cells + blend + p_t partial dot
__global__ void __launch_bounds__(256)
k_recurrent(const float* __restrict__ Whl, const float* __restrict__ Whs,
            const float* __restrict__ Wp, float* __restrict__ out_h,
            float* __restrict__ out_p)
{
    __shared__ float Hs[32][65];
    __shared__ float Ws[128][33];
    int tid = threadIdx.x, warp = tid >> 5, lane = tid & 31;
    int b0 = warp * 8;
    int gtid = blockIdx.x * blockDim.x + tid;
    int nth  = gridDim.x * blockDim.x;

    for (int t = 0; t < L_; ++t) {
        for (int tile = blockIdx.x; tile < 144; tile += gridDim.x) {
            float acc[8][4];
#pragma unroll
            for (int r = 0; r < 8; ++r)
#pragma unroll
                for (int c = 0; c < 4; ++c) acc[r][c] = 0.f;

            int big = (tile < 128);
            int j0, ks0, klen, H, Kdim;
            const float* W;
            const float* hsrc;
            if (big) { j0 = (tile >> 2) * 128; ks0 = (tile & 3) * 256; klen = 256;
                       W = Whl; hsrc = g_hl; Kdim = HL_; H = 4096; }
            else     { int tt = tile - 128; j0 = (tt >> 1) * 128; ks0 = (tt & 1) * 128;
                       klen = 128; W = Whs; hsrc = g_hs; Kdim = HS_; H = 1024; }

            for (int ks = 0; ks < klen; ks += 32) {
#pragma unroll
                for (int i = tid; i < 2048; i += 256) {
                    int kk = i >> 6, bb = i & 63;
                    Hs[kk][bb] = __ldcg(&hsrc[(ks0 + ks + kk) * B_ + bb]);
                }
#pragma unroll
                for (int i = tid; i < 4096; i += 256) {
                    int jj = i >> 5, kk = i & 31;
                    Ws[jj][kk] = W[(size_t)(j0 + jj) * Kdim + ks0 + ks + kk];
                }
                __syncthreads();
#pragma unroll 8
                for (int kk = 0; kk < 32; ++kk) {
                    float wv[4], hv[8];
#pragma unroll
                    for (int c = 0; c < 4; ++c) wv[c] = Ws[lane + 32 * c][kk];
#pragma unroll
                    for (int r = 0; r < 8; ++r) hv[r] = Hs[kk][b0 + r];
#pragma unroll
                    for (int r = 0; r < 8; ++r)
#pragma unroll
                        for (int c = 0; c < 4; ++c) acc[r][c] += hv[r] * wv[c];
                }
                __syncthreads();
            }
            float* dst = (big ? g_gl + (size_t)t * B_ * 4096
                              : g_gs + (size_t)t * B_ * 1024);
#pragma unroll
            for (int r = 0; r < 8; ++r)
#pragma unroll
                for (int c = 0; c < 4; ++c)
                    atomicAdd(&dst[(size_t)(b0 + r) * H + j0 + lane + 32 * c], acc[r][c]);
        }
        grid_sync();

        for (int idx = gtid; idx < B_ * HL_; idx += nth) {
            int b = idx >> 10, k = idx & 1023;
            const float* gl = g_gl + (size_t)t * B_ * 4096 + (size_t)b * 4096;
            float gi = __ldcg(gl + k);
            float gf = __ldcg(gl + 1024 + k);
            float gg = __ldcg(gl + 2048 + k);
            float go = __ldcg(gl + 3072 + k);
            float c_old = __ldcg(&g_cl[k * B_ + b]);
            float h_old = __ldcg(&g_hl[k * B_ + b]);
            float c_new = sigf(gf) * c_old + sigf(gi) * tanhf(gg);
            float h_new = sigf(go) * tanhf(c_new);

            float h_bl, c_bl;
            if (k < HS_) {
                const float* gs = g_gs + (size_t)t * B_ * 1024 + (size_t)b * 1024;
                float si = __ldcg(gs + k);
                float sf = __ldcg(gs + 256 + k);
                float sg = __ldcg(gs + 512 + k);
                float so = __ldcg(gs + 768 + k);
                float cs_old = __ldcg(&g_cs[k * B_ + b]);
                float cs_new = sigf(sf) * cs_old + sigf(si) * tanhf(sg);
                float hs_new = sigf(so) * tanhf(cs_new);
                g_cs[k * B_ + b] = cs_new;
                g_hs[k * B_ + b] = hs_new;
                h_bl = hs_new; c_bl = cs_new;
            } else {
                h_bl = h_old;      // tail of h_blend = previous (carry) h_l
                c_bl = c_new;      // tail of c_blend = c_l_new
            }
            float r0 = g_r[(t * B_ + b) * 2 + 0];
            float r1 = g_r[(t * B_ + b) * 2 + 1];
            float h_next = r0 * h_new + r1 * h_bl;
            float c_next = r0 * c_new + r1 * c_bl;
            g_hl[k * B_ + b] = h_next;
            g_cl[k * B_ + b] = c_next;
            out_h[((size_t)b * L_ + t) * HL_ + k] = h_next;

            // p_t uses h_l_new / c_l_new (unblended); warp covers 32 consecutive k, same b
            float p0 = h_new * Wp[E_ + k] + c_new * Wp[E_ + HL_ + k];
            float p1 = h_new * Wp[2560 + E_ + k] + c_new * Wp[2560 + E_ + HL_ + k];
#pragma unroll
            for (int o = 16; o; o >>= 1) {
                p0 += __shfl_down_sync(0xffffffffu, p0, o);
                p1 += __shfl_down_sync(0xffffffffu, p1, o);
            }
            if (lane == 0) {
                atomicAdd(&out_p[((size_t)b * L_ + t) * 2 + 0], p0);
                atomicAdd(&out_p[((size_t)b * L_ + t) * 2 + 1], p1);
            }
        }
        grid_sync();
    }
}

// ---------- classifier head ----------
__global__ void __launch_bounds__(256)
k_cls(const float* __restrict__ Wc1, const float* __restrict__ bc1,
      const float* __restrict__ Wc2, const float* __restrict__ bc2,
      float* __restrict__ out_logits)
{
    __shared__ float hb[1024];
    __shared__ float zs[512];
    __shared__ float lg[NC_];
    int b = blockIdx.x, tid = threadIdx.x;
    for (int i = tid; i < HL_; i += 256) hb[i] = fmaxf(g_hl[i * B_ + b], 0.f);
    __syncthreads();
    for (int m = tid; m < 512; m += 256) {
        float acc = bc1[m];
        const float* w = Wc1 + (size_t)m * HL_;
        for (int k = 0; k < HL_; ++k) acc += hb[k] * w[k];
        zs[m] = fmaxf(acc, 0.f);
    }
    __syncthreads();
    if (tid < NC_) {
        float acc = bc2[tid];
        const float* w = Wc2 + (size_t)tid * 512;
        for (int m = 0; m < 512; ++m) acc += zs[m] * w[m];
        lg[tid] = acc;
    }
    __syncthreads();
    if (tid == 0) {
        float mx = lg[0];
        for (int n = 1; n < NC_; ++n) mx = fmaxf(mx, lg[n]);
        float e[NC_], s = 0.f;
        for (int n = 0; n < NC_; ++n) { e[n] = expf(lg[n] - mx); s += e[n]; }
        float inv = 1.f / s;
        for (int n = 0; n < NC_; ++n) out_logits[b * NC_ + n] = e[n] * inv;
    }
}

// ---------- p softmax in place ----------
__global__ void k_psoft(float* __restrict__ out_p) {
    int q = blockIdx.x * blockDim.x + threadIdx.x;
    if (q >= B_ * L_) return;
    float p0 = out_p[q * 2], p1 = out_p[q * 2 + 1];
    float m = fmaxf(p0, p1);
    float e0 = expf(p0 - m), e1 = expf(p1 - m);
    float inv = 1.f / (e0 + e1);
    out_p[q * 2 + 0] = e0 * inv;
    out_p[q * 2 + 1] = e1 * inv;
}

// ---------- launch ----------
extern "C" void kernel_launch(void* const* d_in, const int* in_sizes, int n_in,
                              void* d_out, int out_size)
{
    const int*   x    = (const int*)  d_in[0];
    const float* gu   = (const float*)d_in[1];
    const float* emb  = (const float*)d_in[2];
    const float* Wihl = (const float*)d_in[3];
    const float* Whhl = (const float*)d_in[4];
    const float* bihl = (const float*)d_in[5];
    const float* bhhl = (const float*)d_in[6];
    const float* Wihs = (const float*)d_in[7];
    const float* Whhs = (const float*)d_in[8];
    const float* bihs = (const float*)d_in[9];
    const float* bhhs = (const float*)d_in[10];
    const float* Wp   = (const float*)d_in[11];
    const float* bp   = (const float*)d_in[12];
    const float* Wc1  = (const float*)d_in[13];
    const float* bc1  = (const float*)d_in[14];
    const float* Wc2  = (const float*)d_in[15];
    const float* bc2  = (const float*)d_in[16];

    float* out_logits = (float*)d_out;
    float* out_h      = out_logits + (size_t)B_ * NC_;
    float* out_p      = out_h + (size_t)B_ * L_ * HL_;

    float* ggl; cudaGetSymbolAddress((void**)&ggl, g_gl);
    float* ggs; cudaGetSymbolAddress((void**)&ggs, g_gs);

    k_init<<<256, 256>>>(gu);

    {
        dim3 gl(4 * HL_ / 128, (B_ * L_) / 64);   // 32 x 512
        k_ingemm<4 * HL_><<<gl, 256>>>(x, emb, Wihl, bihl, bhhl, ggl);
        dim3 gs(4 * HS_ / 128, (B_ * L_) / 64);   // 8 x 512
        k_ingemm<4 * HS_><<<gs, 256>>>(x, emb, Wihs, bihs, bhhs, ggs);
    }

    k_pe<<<(B_ * L_ * 32 + 255) / 256, 256>>>(x, emb, Wp, bp, out_p);

    k_recurrent<<<144, 256>>>(Whhl, Whhs, Wp, out_h, out_p);

    k_cls<<<B_, 256>>>(Wc1, bc1, Wc2, bc2, out_logits);
    k_psoft<<<(B_ * L_ + 255) / 256, 256>>>(out_p);
}

// round 5
// speedup vs baseline: 1.0993x; 1.0993x over previous
#include <cuda_runtime.h>
#include <cstdint>

#define B_   64
#define L_   512
#define E_   512
#define HL_  1024
#define HS_  256
#define NC_  5

typedef unsigned long long ull;

// packed fp32x2 FMA (FFMA2) — only reachable via PTX
#define FMA2(d, a, b, c) asm("fma.rn.f32x2 %0, %1, %2, %3;" : "=l"(d) : "l"(a), "l"(b), "l"(c))

union F2U { ull u; float2 f; };

// ---------- device scratch (static; no runtime allocation) ----------
__device__ float g_gl[(size_t)L_ * B_ * 4 * HL_];   // gates large: [t][b][4096]
__device__ float g_gs[(size_t)L_ * B_ * 4 * HS_];   // gates small: [t][b][1024]
__device__ float g_r [L_ * B_ * 2];                 // gumbel weights [t][b][2]
__device__ float g_hl[HL_ * B_];                    // states transposed [k][b]
__device__ float g_cl[HL_ * B_];
__device__ float g_hs[HS_ * B_];
__device__ float g_cs[HS_ * B_];
__device__ unsigned int g_bar_arrive = 0;
__device__ unsigned int g_bar_gen    = 0;

__device__ __forceinline__ float sigf(float x) { return 1.0f / (1.0f + expf(-x)); }

__device__ __forceinline__ void grid_sync(void) {
    __syncthreads();
    if (threadIdx.x == 0) {
        unsigned int gen = *((volatile unsigned int*)&g_bar_gen);
        __threadfence();
        unsigned int a = atomicAdd(&g_bar_arrive, 1u);
        if (a == gridDim.x - 1) {
            g_bar_arrive = 0;
            __threadfence();
            atomicAdd(&g_bar_gen, 1u);
        } else {
            while (*((volatile unsigned int*)&g_bar_gen) == gen) { __nanosleep(32); }
        }
        __threadfence();
    }
    __syncthreads();
}

// ---------- init: gumbel-softmax r, zero recurrent state ----------
__global__ void k_init(const float* __restrict__ gu) {
    int n  = gridDim.x * blockDim.x;
    int id = blockIdx.x * blockDim.x + threadIdx.x;
    for (int q = id; q < B_ * L_; q += n) {            // q = b*L + t (gumbel_u is [B,L,2])
        int b = q >> 9, t = q & 511;
        float a0 = -logf(-logf(gu[q * 2 + 0]));
        float a1 = -logf(-logf(gu[q * 2 + 1]));
        float m  = fmaxf(a0, a1);
        float e0 = expf(a0 - m), e1 = expf(a1 - m);
        float inv = 1.0f / (e0 + e1);
        g_r[(t * B_ + b) * 2 + 0] = e0 * inv;
        g_r[(t * B_ + b) * 2 + 1] = e1 * inv;
    }
    for (int q = id; q < HL_ * B_; q += n) { g_hl[q] = 0.f; g_cl[q] = 0.f; }
    for (int q = id; q < HS_ * B_; q += n) { g_hs[q] = 0.f; g_cs[q] = 0.f; }
}

// ---------- input-gate GEMM fused with embedding gather (FFMA2 microkernel) ----------
// out[m][j] = sum_k emb[tok(m)][k]*Wih[j][k] + bih[j]+bhh[j];  m=t*B+b, M=32768, K=512
// tile 64m x 128j, BK=32, 256 thr; per-thread 8m x 2 j-pairs (j = j0 + lane*2 + 64c)
template <int NTOT>
__global__ void __launch_bounds__(256)
k_ingemm(const int* __restrict__ x, const float* __restrict__ emb,
         const float* __restrict__ Wih, const float* __restrict__ bih,
         const float* __restrict__ bhh, float* __restrict__ out)
{
    __shared__ __align__(16) float Asd[32][130];   // duplicated pairs: Asd[kk][2m]=(v,v)
    __shared__ __align__(16) float Wst[32][138];   // transposed: Wst[kk][jj]
    __shared__ int toks[64];

    int tid = threadIdx.x, warp = tid >> 5, lane = tid & 31;
    int m0 = blockIdx.y * 64, j0 = blockIdx.x * 128, b0 = warp * 8;

    if (tid < 64) { int m = m0 + tid; toks[tid] = x[(m & 63) * L_ + (m >> 6)]; }
    __syncthreads();

    ull acc[8][2];
#pragma unroll
    for (int r = 0; r < 8; ++r) { acc[r][0] = 0ull; acc[r][1] = 0ull; }

    float ph[8], pw[16];
    // prologue: prefetch chunk 0
#pragma unroll
    for (int s = 0; s < 8; ++s) {
        int i = tid + s * 256, mm = i >> 5, kk = i & 31;
        ph[s] = __ldg(&emb[(size_t)toks[mm] * E_ + kk]);
    }
#pragma unroll
    for (int s = 0; s < 16; ++s) {
        int i = tid + s * 256, jj = i >> 5, kk = i & 31;
        pw[s] = __ldg(&Wih[(size_t)(j0 + jj) * E_ + kk]);
    }

    for (int ch = 0; ch < E_ / 32; ++ch) {
#pragma unroll
        for (int s = 0; s < 8; ++s) {
            int i = tid + s * 256, mm = i >> 5, kk = i & 31;
            *(float2*)&Asd[kk][mm * 2] = make_float2(ph[s], ph[s]);
        }
#pragma unroll
        for (int s = 0; s < 16; ++s) {
            int i = tid + s * 256, jj = i >> 5, kk = i & 31;
            Wst[kk][jj] = pw[s];
        }
        __syncthreads();

        if (ch + 1 < E_ / 32) {
            int ks = (ch + 1) * 32;
#pragma unroll
            for (int s = 0; s < 8; ++s) {
                int i = tid + s * 256, mm = i >> 5, kk = i & 31;
                ph[s] = __ldg(&emb[(size_t)toks[mm] * E_ + ks + kk]);
            }
#pragma unroll
            for (int s = 0; s < 16; ++s) {
                int i = tid + s * 256, jj = i >> 5, kk = i & 31;
                pw[s] = __ldg(&Wih[(size_t)(j0 + jj) * E_ + ks + kk]);
            }
        }

#pragma unroll 4
        for (int kk = 0; kk < 32; ++kk) {
            ull w0 = *(const ull*)&Wst[kk][lane * 2];
            ull w1 = *(const ull*)&Wst[kk][lane * 2 + 64];
#pragma unroll
            for (int r = 0; r < 8; ++r) {
                ull av = *(const ull*)&Asd[kk][(b0 + r) * 2];
                FMA2(acc[r][0], av, w0, acc[r][0]);
                FMA2(acc[r][1], av, w1, acc[r][1]);
            }
        }
        __syncthreads();
    }

#pragma unroll
    for (int c = 0; c < 2; ++c) {
        int j = j0 + lane * 2 + 64 * c;
        float2 bi = *(const float2*)&bih[j];
        float2 bh = *(const float2*)&bhh[j];
        float bx = bi.x + bh.x, by = bi.y + bh.y;
#pragma unroll
        for (int r = 0; r < 8; ++r) {
            F2U u; u.u = acc[r][c];
            *(float2*)&out[(size_t)(m0 + b0 + r) * NTOT + j] =
                make_float2(u.f.x + bx, u.f.y + by);
        }
    }
}

// ---------- p_t embedding part: out_p[b*L+t][c] = b_p[c] + e . W_p[c][0:512] ----------
__global__ void __launch_bounds__(256)
k_pe(const int* __restrict__ x, const float* __restrict__ emb,
     const float* __restrict__ Wp, const float* __restrict__ bp,
     float* __restrict__ out_p)
{
    int gw = (blockIdx.x * blockDim.x + threadIdx.x) >> 5;   // gw = b*L + t
    int lane = threadIdx.x & 31;
    if (gw >= B_ * L_) return;
    const float* e = emb + (size_t)x[gw] * E_;
    float s0 = 0.f, s1 = 0.f;
    for (int k = lane; k < E_; k += 32) {
        float ev = e[k];
        s0 += ev * Wp[k];
        s1 += ev * Wp[2560 + k];
    }
#pragma unroll
    for (int o = 16; o; o >>= 1) {
        s0 += __shfl_down_sync(0xffffffffu, s0, o);
        s1 += __shfl_down_sync(0xffffffffu, s1, o);
    }
    if (lane == 0) {
        out_p[(size_t)gw * 2 + 0] = s0 + bp[0];
        out_p[(size_t)gw * 2 + 1] = s1 + bp[1];
    }
}

// ---------- persistent recurrence ----------
// phase1: K-split recurrent GEMM (FFMA2) -> RED.ADD into gate buffers
//   tiles: 128 large (j-blk 128 of 4096, K-chunk 256 of 1024) + 16 small = 144 = gridDim
// phase2: fused LSTM cells + blend + p_t partial dot
__global__ void __launch_bounds__(256)
k_recurrent(const float* __restrict__ Whl, const float* __restrict__ Whs,
            const float* __restrict__ Wp, float* __restrict__ out_h,
            float* __restrict__ out_p)
{
    __shared__ __align__(16) float Asd[32][130];
    __shared__ __align__(16) float Wst[32][138];

    int tid = threadIdx.x, warp = tid >> 5, lane = tid & 31;
    int b0 = warp * 8;
    int gtid = blockIdx.x * blockDim.x + tid;
    int nth  = gridDim.x * blockDim.x;

    // fixed tile per CTA
    int tile = blockIdx.x;
    int big = (tile < 128);
    int j0, ks0, nch, Kdim, H;
    const float* W;
    const float* hsrc;
    if (big) { j0 = (tile >> 2) * 128; ks0 = (tile & 3) * 256; nch = 8;
               W = Whl; hsrc = g_hl; Kdim = HL_; H = 4096; }
    else     { int tt = tile - 128;   j0 = (tt >> 1) * 128;  ks0 = (tt & 1) * 128; nch = 4;
               W = Whs; hsrc = g_hs; Kdim = HS_; H = 1024; }

    for (int t = 0; t < L_; ++t) {
        // ---------------- phase 1 ----------------
        ull acc[8][2];
#pragma unroll
        for (int r = 0; r < 8; ++r) { acc[r][0] = 0ull; acc[r][1] = 0ull; }

        float ph[8], pw[16];
#pragma unroll
        for (int s = 0; s < 8; ++s) {
            int i = tid + s * 256, kk = i >> 6, bb = i & 63;
            ph[s] = __ldcg(&hsrc[(ks0 + kk) * B_ + bb]);
        }
#pragma unroll
        for (int s = 0; s < 16; ++s) {
            int i = tid + s * 256, jj = i >> 5, kk = i & 31;
            pw[s] = __ldg(&W[(size_t)(j0 + jj) * Kdim + ks0 + kk]);
        }

        for (int ch = 0; ch < nch; ++ch) {
#pragma unroll
            for (int s = 0; s < 8; ++s) {
                int i = tid + s * 256, kk = i >> 6, bb = i & 63;
                *(float2*)&Asd[kk][bb * 2] = make_float2(ph[s], ph[s]);
            }
#pragma unroll
            for (int s = 0; s < 16; ++s) {
                int i = tid + s * 256, jj = i >> 5, kk = i & 31;
                Wst[kk][jj] = pw[s];
            }
            __syncthreads();

            if (ch + 1 < nch) {
                int ks = ks0 + (ch + 1) * 32;
#pragma unroll
                for (int s = 0; s < 8; ++s) {
                    int i = tid + s * 256, kk = i >> 6, bb = i & 63;
                    ph[s] = __ldcg(&hsrc[(ks + kk) * B_ + bb]);
                }
#pragma unroll
                for (int s = 0; s < 16; ++s) {
                    int i = tid + s * 256, jj = i >> 5, kk = i & 31;
                    pw[s] = __ldg(&W[(size_t)(j0 + jj) * Kdim + ks + kk]);
                }
            }

#pragma unroll 4
            for (int kk = 0; kk < 32; ++kk) {
                ull w0 = *(const ull*)&Wst[kk][lane * 2];
                ull w1 = *(const ull*)&Wst[kk][lane * 2 + 64];
#pragma unroll
                for (int r = 0; r < 8; ++r) {
                    ull av = *(const ull*)&Asd[kk][(b0 + r) * 2];
                    FMA2(acc[r][0], av, w0, acc[r][0]);
                    FMA2(acc[r][1], av, w1, acc[r][1]);
                }
            }
            __syncthreads();
        }

        {
            float* dst = (big ? g_gl + (size_t)t * B_ * 4096
                              : g_gs + (size_t)t * B_ * 1024);
#pragma unroll
            for (int c = 0; c < 2; ++c) {
                int j = j0 + lane * 2 + 64 * c;
#pragma unroll
                for (int r = 0; r < 8; ++r) {
                    F2U u; u.u = acc[r][c];
                    atomicAdd(&dst[(size_t)(b0 + r) * H + j],     u.f.x);
                    atomicAdd(&dst[(size_t)(b0 + r) * H + j + 1], u.f.y);
                }
            }
        }
        grid_sync();

        // ---------------- phase 2 ----------------
        for (int idx = gtid; idx < B_ * HL_; idx += nth) {
            int b = idx >> 10, k = idx & 1023;
            const float* gl = g_gl + (size_t)t * B_ * 4096 + (size_t)b * 4096;
            float gi = __ldcg(gl + k);
            float gf = __ldcg(gl + 1024 + k);
            float gg = __ldcg(gl + 2048 + k);
            float go = __ldcg(gl + 3072 + k);
            float c_old = __ldcg(&g_cl[k * B_ + b]);
            float h_old = __ldcg(&g_hl[k * B_ + b]);
            float c_new = sigf(gf) * c_old + sigf(gi) * tanhf(gg);
            float h_new = sigf(go) * tanhf(c_new);

            float h_bl, c_bl;
            if (k < HS_) {
                const float* gs = g_gs + (size_t)t * B_ * 1024 + (size_t)b * 1024;
                float si = __ldcg(gs + k);
                float sf = __ldcg(gs + 256 + k);
                float sg = __ldcg(gs + 512 + k);
                float so = __ldcg(gs + 768 + k);
                float cs_old = __ldcg(&g_cs[k * B_ + b]);
                float cs_new = sigf(sf) * cs_old + sigf(si) * tanhf(sg);
                float hs_new = sigf(so) * tanhf(cs_new);
                g_cs[k * B_ + b] = cs_new;
                g_hs[k * B_ + b] = hs_new;
                h_bl = hs_new; c_bl = cs_new;
            } else {
                h_bl = h_old;      // tail of h_blend = previous (carry) h_l
                c_bl = c_new;      // tail of c_blend = c_l_new
            }
            float r0 = g_r[(t * B_ + b) * 2 + 0];
            float r1 = g_r[(t * B_ + b) * 2 + 1];
            float h_next = r0 * h_new + r1 * h_bl;
            float c_next = r0 * c_new + r1 * c_bl;
            g_hl[k * B_ + b] = h_next;
            g_cl[k * B_ + b] = c_next;
            out_h[((size_t)b * L_ + t) * HL_ + k] = h_next;

            // p_t uses h_l_new / c_l_new (unblended)
            float p0 = h_new * Wp[E_ + k] + c_new * Wp[E_ + HL_ + k];
            float p1 = h_new * Wp[2560 + E_ + k] + c_new * Wp[2560 + E_ + HL_ + k];
#pragma unroll
            for (int o = 16; o; o >>= 1) {
                p0 += __shfl_down_sync(0xffffffffu, p0, o);
                p1 += __shfl_down_sync(0xffffffffu, p1, o);
            }
            if (lane == 0) {
                atomicAdd(&out_p[((size_t)b * L_ + t) * 2 + 0], p0);
                atomicAdd(&out_p[((size_t)b * L_ + t) * 2 + 1], p1);
            }
        }
        grid_sync();
    }
}

// ---------- classifier head ----------
__global__ void __launch_bounds__(256)
k_cls(const float* __restrict__ Wc1, const float* __restrict__ bc1,
      const float* __restrict__ Wc2, const float* __restrict__ bc2,
      float* __restrict__ out_logits)
{
    __shared__ float hb[1024];
    __shared__ float zs[512];
    __shared__ float lg[NC_];
    int b = blockIdx.x, tid = threadIdx.x;
    for (int i = tid; i < HL_; i += 256) hb[i] = fmaxf(g_hl[i * B_ + b], 0.f);
    __syncthreads();
    for (int m = tid; m < 512; m += 256) {
        float acc = bc1[m];
        const float* w = Wc1 + (size_t)m * HL_;
        for (int k = 0; k < HL_; ++k) acc += hb[k] * w[k];
        zs[m] = fmaxf(acc, 0.f);
    }
    __syncthreads();
    if (tid < NC_) {
        float acc = bc2[tid];
        const float* w = Wc2 + (size_t)tid * 512;
        for (int m = 0; m < 512; ++m) acc += zs[m] * w[m];
        lg[tid] = acc;
    }
    __syncthreads();
    if (tid == 0) {
        float mx = lg[0];
        for (int n = 1; n < NC_; ++n) mx = fmaxf(mx, lg[n]);
        float e[NC_], s = 0.f;
        for (int n = 0; n < NC_; ++n) { e[n] = expf(lg[n] - mx); s += e[n]; }
        float inv = 1.f / s;
        for (int n = 0; n < NC_; ++n) out_logits[b * NC_ + n] = e[n] * inv;
    }
}

// ---------- p softmax in place ----------
__global__ void k_psoft(float* __restrict__ out_p) {
    int q = blockIdx.x * blockDim.x + threadIdx.x;
    if (q >= B_ * L_) return;
    float p0 = out_p[q * 2], p1 = out_p[q * 2 + 1];
    float m = fmaxf(p0, p1);
    float e0 = expf(p0 - m), e1 = expf(p1 - m);
    float inv = 1.f / (e0 + e1);
    out_p[q * 2 + 0] = e0 * inv;
    out_p[q * 2 + 1] = e1 * inv;
}

// ---------- launch ----------
extern "C" void kernel_launch(void* const* d_in, const int* in_sizes, int n_in,
                              void* d_out, int out_size)
{
    const int*   x    = (const int*)  d_in[0];
    const float* gu   = (const float*)d_in[1];
    const float* emb  = (const float*)d_in[2];
    const float* Wihl = (const float*)d_in[3];
    const float* Whhl = (const float*)d_in[4];
    const float* bihl = (const float*)d_in[5];
    const float* bhhl = (const float*)d_in[6];
    const float* Wihs = (const float*)d_in[7];
    const float* Whhs = (const float*)d_in[8];
    const float* bihs = (const float*)d_in[9];
    const float* bhhs = (const float*)d_in[10];
    const float* Wp   = (const float*)d_in[11];
    const float* bp   = (const float*)d_in[12];
    const float* Wc1  = (const float*)d_in[13];
    const float* bc1  = (const float*)d_in[14];
    const float* Wc2  = (const float*)d_in[15];
    const float* bc2  = (const float*)d_in[16];

    float* out_logits = (float*)d_out;
    float* out_h      = out_logits + (size_t)B_ * NC_;
    float* out_p      = out_h + (size_t)B_ * L_ * HL_;

    float* ggl; cudaGetSymbolAddress((void**)&ggl, g_gl);
    float* ggs; cudaGetSymbolAddress((void**)&ggs, g_gs);

    k_init<<<256, 256>>>(gu);

    {
        dim3 gl(4 * HL_ / 128, (B_ * L_) / 64);   // 32 x 512
        k_ingemm<4 * HL_><<<gl, 256>>>(x, emb, Wihl, bihl, bhhl, ggl);
        dim3 gs(4 * HS_ / 128, (B_ * L_) / 64);   // 8 x 512
        k_ingemm<4 * HS_><<<gs, 256>>>(x, emb, Wihs, bihs, bhhs, ggs);
    }

    k_pe<<<(B_ * L_ * 32 + 255) / 256, 256>>>(x, emb, Wp, bp, out_p);

    k_recurrent<<<144, 256>>>(Whhl, Whhs, Wp, out_h, out_p);

    k_cls<<<B_, 256>>>(Wc1, bc1, Wc2, bc2, out_logits);
    k_psoft<<<(B_ * L_ + 255) / 256, 256>>>(out_p);
}